// round 15
// baseline (speedup 1.0000x reference)
#include <cuda_runtime.h>
#include <math.h>
#include <stdint.h>

#define H 128
#define KEXT 144
#define EAP 12            // easum row: 9 attrs, deg, cnt1, pad
#define NG 256
#define NT 40
#define MAXN 50048
#define MAXE 600064
#define BN_EPS 1e-5f
#define APAD 132
#define BPAD 136

// ---------------- scratch ----------------------------------------------------
__device__ float g_h[MAXN * H];
__device__ float g_agg[MAXN * KEXT];
__device__ float g_easum[MAXN * EAP];
__device__ float g_w1ext[KEXT * 2 * H];
__device__ float g_umat[13 * 2 * H];
__device__ float g_poolz[NG * 2 * H];
__device__ float g_wf[NT * 2 * H];
__device__ float g_bf[NT];
__device__ int   g_cnt[NG];
__device__ int   g_deg[MAXN];
__device__ int   g_off[MAXN];       // per-block-exclusive prefix
__device__ int   g_bsum[256];       // exclusive block sums
__device__ int   g_fill[MAXN];
__device__ int   g_csrc[MAXE];      // src node per CSR slot
__device__ int   g_ceid[MAXE];      // edge id per CSR slot

// ---------------- helpers ---------------------------------------------------
__device__ __forceinline__ void red_add_v2(float* p, float2 v) {
    asm volatile("red.global.add.v2.f32 [%0], {%1,%2};"
                 :: "l"(p), "f"(v.x), "f"(v.y) : "memory");
}
__device__ __forceinline__ uint32_t pack2(float lo, float hi) {
    uint32_t r;
    asm("cvt.rn.bf16x2.f32 %0, %1, %2;" : "=r"(r) : "f"(hi), "f"(lo));
    return r;
}
__device__ __forceinline__ void split2(float f0, float f1, uint32_t& hi, uint32_t& lo) {
    hi = pack2(f0, f1);
    float h0 = __uint_as_float(hi << 16);
    float h1 = __uint_as_float(hi & 0xffff0000u);
    lo = pack2(f0 - h0, f1 - h1);
}
__device__ __forceinline__ void mma_bf16(float* d, const uint32_t* a, const uint32_t* b) {
    asm volatile("mma.sync.aligned.m16n8k16.row.col.f32.bf16.bf16.f32 "
                 "{%0,%1,%2,%3},{%4,%5,%6,%7},{%8,%9},{%0,%1,%2,%3};"
                 : "+f"(d[0]), "+f"(d[1]), "+f"(d[2]), "+f"(d[3])
                 : "r"(a[0]), "r"(a[1]), "r"(a[2]), "r"(a[3]),
                   "r"(b[0]), "r"(b[1]));
}

// ---------------- setup kernels ----------------------------------------------
__global__ void deg_count(const int* __restrict__ ei, int E) {
    int e = blockIdx.x * blockDim.x + threadIdx.x;
    if (e >= E) return;
    atomicAdd(&g_deg[__ldg(ei + e)], 1);
}

// scan1: per-block exclusive prefix of deg + block totals; also zero g_fill and
// accumulate per-graph node counts (one thread per node).
__global__ void scan1(const int* __restrict__ batch, int N) {
    int b = blockIdx.x, t = threadIdx.x;
    int i = b * 256 + t;
    int v = (i < N) ? g_deg[i] : 0;
    __shared__ int sm[256];
    sm[t] = v;
    __syncthreads();
#pragma unroll
    for (int off = 1; off < 256; off <<= 1) {
        int xx = (t >= off) ? sm[t - off] : 0;
        __syncthreads();
        sm[t] += xx;
        __syncthreads();
    }
    if (i < N) {
        g_off[i] = sm[t] - v;
        g_fill[i] = 0;
        atomicAdd(&g_cnt[batch[i]], 1);
    }
    if (t == 255) g_bsum[b] = sm[255];
}
__global__ void scan2(int B) {
    int t = threadIdx.x;
    int v = (t < B) ? g_bsum[t] : 0;
    __shared__ int sm[256];
    sm[t] = v;
    __syncthreads();
#pragma unroll
    for (int off = 1; off < 256; off <<= 1) {
        int xx = (t >= off) ? sm[t - off] : 0;
        __syncthreads();
        sm[t] += xx;
        __syncthreads();
    }
    if (t < B) g_bsum[t] = sm[t] - v;
}

__global__ void scatter(const int* __restrict__ ei, int E) {
    int e = blockIdx.x * blockDim.x + threadIdx.x;
    if (e >= E) return;
    int d = __ldg(ei + e);
    int slot = atomicAdd(&g_fill[d], 1);
    int base = __ldg(g_off + d) + __ldg(g_bsum + (d >> 8));
    g_csrc[base + slot] = __ldg(ei + E + e);
    g_ceid[base + slot] = e;
}

// easum gather: warp per node; lanes gather attrs by edge-id + x[src]; warp
// shfl-reduce; lane 0 writes the 48B row once. No global atomics.
__global__ void easum_gather(const float* __restrict__ ea, const int* __restrict__ x,
                             int N, int E) {
    int t = blockIdx.x * blockDim.x + threadIdx.x;
    int n = t >> 5;
    if (n >= N) return;
    int lane = t & 31;
    int beg = __ldg(g_off + n) + __ldg(g_bsum + (n >> 8));
    int end = (n + 1 < N) ? (__ldg(g_off + n + 1) + __ldg(g_bsum + ((n + 1) >> 8))) : E;
    float p[10];
#pragma unroll
    for (int j = 0; j < 10; j++) p[j] = 0.f;
    for (int e = beg + lane; e < end; e += 32) {
        int eid = __ldg(g_ceid + e);
        int src = __ldg(g_csrc + e);
        const float* a = ea + (size_t)eid * 9;
#pragma unroll
        for (int j = 0; j < 9; j++) p[j] += __ldg(a + j);
        p[9] += (float)__ldg(x + src);
    }
#pragma unroll
    for (int j = 0; j < 10; j++)
#pragma unroll
        for (int off = 16; off; off >>= 1)
            p[j] += __shfl_down_sync(0xffffffffu, p[j], off);
    if (lane == 0) {
        float* s = g_easum + (size_t)n * EAP;
        *(float4*)(s)     = make_float4(p[0], p[1], p[2], p[3]);
        *(float4*)(s + 4) = make_float4(p[4], p[5], p[6], p[7]);
        *(float4*)(s + 8) = make_float4(p[8], (float)(end - beg), p[9], 0.f);
    }
}

// ---- merged prep: blocks [0,144) w1ext | [144,157) umat | [157,414) wf/bf ---
__global__ void prep_all(const float* __restrict__ emb,
                         const float* __restrict__ enc_w0, const float* __restrict__ enc_b0,
                         const float* __restrict__ w1_0,   const float* __restrict__ b1_0,
                         const float* __restrict__ gm0,    const float* __restrict__ bt0,
                         const float* __restrict__ mn0,    const float* __restrict__ vr0,
                         const float* __restrict__ enc_w1, const float* __restrict__ enc_b1,
                         const float* __restrict__ w1_1,   const float* __restrict__ b1_1,
                         const float* __restrict__ gm1,    const float* __restrict__ bt1,
                         const float* __restrict__ mn1,    const float* __restrict__ vr1,
                         const float* __restrict__ w2_1,   const float* __restrict__ b2_1,
                         const float* __restrict__ pw,     const float* __restrict__ pb,
                         const int* __restrict__ sli_p,    const int* __restrict__ slt_p) {
    int b = blockIdx.x;
    int tid = threadIdx.x;
    if (b < 144) {
        int k = b, c = tid;
        float sc = gm1[c] * rsqrtf(vr1[c] + BN_EPS);
        float sh = (b1_1[c] - mn1[c]) * sc + bt1[c];
        if (k < 128) {
            g_w1ext[k * 256 + c] = w1_1[k * 256 + c] * sc;
        } else if (k < 139) {
            __shared__ float f[128];
            int j = k - 128;
            if (c < 128) {
                float fv;
                if (j < 9)       fv = enc_w1[j * 128 + c];
                else if (j == 9) fv = enc_b1[c];
                else             fv = (float)(*slt_p) * enc_w1[(*sli_p) * 128 + c];
                f[c] = fv;
            }
            __syncthreads();
            float s = 0.f;
            const float* wb = w1_1 + 128 * 256 + c;
#pragma unroll 16
            for (int i = 0; i < 128; i++) s += f[i] * wb[i * 256];
            g_w1ext[k * 256 + c] = s * sc + (k == 138 ? sh : 0.f);
        } else {
            g_w1ext[k * 256 + c] = 0.f;
        }
    } else if (b < 157) {
        int r = b - 144, c = tid;
        __shared__ float f[128];
        if (c < 128) {
            float fv;
            if (r < 2)        fv = emb[r * 128 + c];
            else if (r < 11)  fv = enc_w0[(r - 2) * 128 + c];
            else if (r == 11) fv = enc_b0[c];
            else              fv = (float)(*slt_p) * enc_w0[(*sli_p) * 128 + c];
            f[c] = fv;
        }
        __syncthreads();
        int base = (r < 2) ? 0 : 128;
        float s = 0.f;
        const float* wb = w1_0 + base * 256 + c;
#pragma unroll 16
        for (int i = 0; i < 128; i++) s += f[i] * wb[i * 256];
        float sc = gm0[c] * rsqrtf(vr0[c] + BN_EPS);
        float sh = (b1_0[c] - mn0[c]) * sc + bt0[c];
        g_umat[r * 256 + c] = s * sc + (r == 12 ? sh : 0.f);
    } else {
        int k = b - 157;
        __shared__ float ws[128];
        if (tid < 128) ws[tid] = (k < 256) ? w2_1[(size_t)k * 128 + tid] : b2_1[tid];
        __syncthreads();
        int w = tid >> 5, lane = tid & 31;
        float acc[5] = {0.f, 0.f, 0.f, 0.f, 0.f};
#pragma unroll
        for (int j = 0; j < 4; j++) {
            int i = j * 32 + lane;
            float wv = ws[i];
#pragma unroll
            for (int u = 0; u < 5; u++) {
                int t = w * 5 + u;
                acc[u] += wv * (__ldg(pw + i * NT + t) + __ldg(pw + (i + 128) * NT + t));
            }
        }
#pragma unroll
        for (int u = 0; u < 5; u++)
#pragma unroll
            for (int off = 16; off; off >>= 1)
                acc[u] += __shfl_down_sync(0xffffffffu, acc[u], off);
        if (lane == 0) {
#pragma unroll
            for (int u = 0; u < 5; u++) {
                int t = w * 5 + u;
                if (k < 256) g_wf[t * 256 + k] = acc[u];
                else         g_bf[t] = acc[u] + pb[t];
            }
        }
    }
}

// layer-1 neighbor gather (warp per node, 8 edges in flight)
__global__ void aggregate(int N, int E) {
    int t = blockIdx.x * blockDim.x + threadIdx.x;
    int n = t >> 5;
    if (n >= N) return;
    int lane = t & 31;
    float4 acc = *(const float4*)(g_h + (size_t)n * H + lane * 4);  // self loop
    int beg = __ldg(g_off + n) + __ldg(g_bsum + (n >> 8));
    int end = (n + 1 < N) ? (__ldg(g_off + n + 1) + __ldg(g_bsum + ((n + 1) >> 8))) : E;
    int e = beg;
    for (; e + 8 <= end; e += 8) {
        int s[8];
#pragma unroll
        for (int k = 0; k < 8; k++) s[k] = __ldg(g_csrc + e + k);
        float4 v[8];
#pragma unroll
        for (int k = 0; k < 8; k++)
            v[k] = *(const float4*)(g_h + (size_t)s[k] * H + lane * 4);
#pragma unroll
        for (int k = 0; k < 8; k++) {
            acc.x += v[k].x; acc.y += v[k].y; acc.z += v[k].z; acc.w += v[k].w;
        }
    }
    if (e + 4 <= end) {
        int s[4];
#pragma unroll
        for (int k = 0; k < 4; k++) s[k] = __ldg(g_csrc + e + k);
        float4 v[4];
#pragma unroll
        for (int k = 0; k < 4; k++)
            v[k] = *(const float4*)(g_h + (size_t)s[k] * H + lane * 4);
#pragma unroll
        for (int k = 0; k < 4; k++) {
            acc.x += v[k].x; acc.y += v[k].y; acc.z += v[k].z; acc.w += v[k].w;
        }
        e += 4;
    }
    for (; e < end; e++) {
        int s0 = __ldg(g_csrc + e);
        float4 v0 = *(const float4*)(g_h + (size_t)s0 * H + lane * 4);
        acc.x += v0.x; acc.y += v0.y; acc.z += v0.z; acc.w += v0.w;
    }
    *(float4*)(g_agg + (size_t)n * KEXT + lane * 4) = acc;
    if (lane < 4) {
        const float* s = g_easum + (size_t)n * EAP;
        float4 ex;
        if (lane == 0)      ex = make_float4(s[0], s[1], s[2], s[3]);
        else if (lane == 1) ex = make_float4(s[4], s[5], s[6], s[7]);
        else if (lane == 2) ex = make_float4(s[8], s[9] + 1.f, 1.f, 0.f);
        else                ex = make_float4(0.f, 0.f, 0.f, 0.f);
        *(float4*)(g_agg + (size_t)n * KEXT + 128 + lane * 4) = ex;
    }
}

// ---------------- GEMM0 with fused rank-13 A producer -------------------------
__global__ void __launch_bounds__(256, 2)
gemm_aff(const int* __restrict__ x, const float* __restrict__ B /*w2_0 [256,128]*/,
         const float* __restrict__ shift /*b2_0*/, int M) {
    const int N = 128, K = 256;
    __shared__ uint32_t Ah[2][8][APAD], Al[2][8][APAD];
    __shared__ uint32_t Bh[2][8][BPAD], Bl[2][8][BPAD];
    __shared__ float U[13][256];
    __shared__ float coef[128][14];
    int bm = blockIdx.x * 128;
    int tid = threadIdx.x;
    int wid = tid >> 5, lane = tid & 31;
    int gid = lane >> 2, tig = lane & 3;
    int wm = (wid >> 2) * 64, wn = (wid & 3) * 32;

    int arow = tid >> 2, aq = tid & 3;
    int bkp = tid >> 5, bc4 = (tid & 31) * 4;

    for (int idx = tid; idx < 13 * 256; idx += 256)
        U[idx >> 8][idx & 255] = g_umat[idx];
    if (tid < 128) {
        int n = bm + tid;
        if (n < M) {
            const float* s = g_easum + (size_t)n * EAP;
            float deg = s[9], cnt1 = s[10];
            int xv = __ldg(x + n);
            coef[tid][0] = deg - cnt1 + (xv == 0 ? 1.f : 0.f);
            coef[tid][1] = cnt1 + (xv == 1 ? 1.f : 0.f);
#pragma unroll
            for (int j = 0; j < 9; j++) coef[tid][2 + j] = s[j];
            coef[tid][11] = deg + 1.f;
            coef[tid][12] = 1.f;
        } else {
#pragma unroll
            for (int j = 0; j < 13; j++) coef[tid][j] = 0.f;
        }
    }

    float acc[4][4][4];
#pragma unroll
    for (int i = 0; i < 4; i++)
#pragma unroll
        for (int j = 0; j < 4; j++)
#pragma unroll
            for (int r = 0; r < 4; r++) acc[i][j][r] = 0.f;

    float4 ra[2], rb[2];
    __syncthreads();   // U/coef ready

    auto compute_a = [&](int k0) {
#pragma unroll
        for (int i = 0; i < 2; i++) {
            int r = arow + i * 64;
            float v[4];
#pragma unroll
            for (int kk = 0; kk < 4; kk++) {
                int k = k0 + aq * 4 + kk;
                float s = 0.f;
#pragma unroll
                for (int j = 0; j < 13; j++) s += coef[r][j] * U[j][k];
                v[kk] = fmaxf(s, 0.f);
            }
            ra[i] = make_float4(v[0], v[1], v[2], v[3]);
        }
    };
    auto store_tiles = [&](int buf) {
#pragma unroll
        for (int i = 0; i < 2; i++) {
            uint32_t h0, l0, h1, l1;
            split2(ra[i].x, ra[i].y, h0, l0);
            split2(ra[i].z, ra[i].w, h1, l1);
            int r = arow + i * 64;
            Ah[buf][aq * 2][r] = h0;     Al[buf][aq * 2][r] = l0;
            Ah[buf][aq * 2 + 1][r] = h1; Al[buf][aq * 2 + 1][r] = l1;
        }
        uint32_t h[4], l[4];
        split2(rb[0].x, rb[1].x, h[0], l[0]);
        split2(rb[0].y, rb[1].y, h[1], l[1]);
        split2(rb[0].z, rb[1].z, h[2], l[2]);
        split2(rb[0].w, rb[1].w, h[3], l[3]);
        *(uint4*)&Bh[buf][bkp][bc4] = make_uint4(h[0], h[1], h[2], h[3]);
        *(uint4*)&Bl[buf][bkp][bc4] = make_uint4(l[0], l[1], l[2], l[3]);
    };

    {
        rb[0] = *(const float4*)(B + (size_t)(2 * bkp) * N + bc4);
        rb[1] = *(const float4*)(B + (size_t)(2 * bkp + 1) * N + bc4);
        compute_a(0);
        store_tiles(0);
    }
    __syncthreads();

    const int nch = K / 16;
    for (int c = 0; c < nch; c++) {
        int cur = c & 1;
        if (c + 1 < nch) {
            int k0 = (c + 1) * 16;
            rb[0] = *(const float4*)(B + (size_t)(k0 + 2 * bkp) * N + bc4);
            rb[1] = *(const float4*)(B + (size_t)(k0 + 2 * bkp + 1) * N + bc4);
        }
        {
            uint32_t ahi[4][4], alo[4][4];
#pragma unroll
            for (int mi = 0; mi < 4; mi++) {
                int r = wm + mi * 16 + gid;
                ahi[mi][0] = Ah[cur][tig][r];     alo[mi][0] = Al[cur][tig][r];
                ahi[mi][1] = Ah[cur][tig][r + 8]; alo[mi][1] = Al[cur][tig][r + 8];
                ahi[mi][2] = Ah[cur][tig + 4][r];     alo[mi][2] = Al[cur][tig + 4][r];
                ahi[mi][3] = Ah[cur][tig + 4][r + 8]; alo[mi][3] = Al[cur][tig + 4][r + 8];
            }
            uint32_t bhi[4][2], blo[4][2];
#pragma unroll
            for (int ni = 0; ni < 4; ni++) {
                int cc = wn + ni * 8 + gid;
                bhi[ni][0] = Bh[cur][tig][cc];     blo[ni][0] = Bl[cur][tig][cc];
                bhi[ni][1] = Bh[cur][tig + 4][cc]; blo[ni][1] = Bl[cur][tig + 4][cc];
            }
#pragma unroll
            for (int mi = 0; mi < 4; mi++)
#pragma unroll
                for (int ni = 0; ni < 4; ni++) {
                    mma_bf16(acc[mi][ni], ahi[mi], bhi[ni]);
                    mma_bf16(acc[mi][ni], alo[mi], bhi[ni]);
                    mma_bf16(acc[mi][ni], ahi[mi], blo[ni]);
                }
        }
        if (c + 1 < nch) {
            compute_a((c + 1) * 16);
            __syncthreads();
            store_tiles(1 - cur);
            __syncthreads();
        }
    }

#pragma unroll
    for (int ni = 0; ni < 4; ni++) {
        int col = wn + ni * 8 + tig * 2;
        float t0 = __ldg(shift + col), t1 = __ldg(shift + col + 1);
#pragma unroll
        for (int mi = 0; mi < 4; mi++) {
            int r0 = bm + wm + mi * 16 + gid;
            float2 v0 = make_float2(fmaxf(acc[mi][ni][0] + t0, 0.f), fmaxf(acc[mi][ni][1] + t1, 0.f));
            float2 v1 = make_float2(fmaxf(acc[mi][ni][2] + t0, 0.f), fmaxf(acc[mi][ni][3] + t1, 0.f));
            if (r0 < M)     *(float2*)(g_h + (size_t)r0 * N + col) = v0;
            if (r0 + 8 < M) *(float2*)(g_h + (size_t)(r0 + 8) * N + col) = v1;
        }
    }
}

// ---------------- pooled GEMM1 (bf16 hi/lo split, red.v2 epilogue) ------------
__global__ void __launch_bounds__(256, 2)
gemm_tc(const float* __restrict__ A, const float* __restrict__ B,
        int M, int N, int K,
        const int* __restrict__ batchmap, float* __restrict__ pool) {
    __shared__ uint32_t Ah[2][8][APAD], Al[2][8][APAD];
    __shared__ uint32_t Bh[2][8][BPAD], Bl[2][8][BPAD];
    int bm = blockIdx.x * 128, bn = blockIdx.y * 128;
    int tid = threadIdx.x;
    int wid = tid >> 5, lane = tid & 31;
    int gid = lane >> 2, tig = lane & 3;
    int wm = (wid >> 2) * 64, wn = (wid & 3) * 32;

    int arow = tid >> 2, aq = tid & 3;
    int bkp = tid >> 5, bc4 = (tid & 31) * 4;

    float acc[4][4][4];
#pragma unroll
    for (int i = 0; i < 4; i++)
#pragma unroll
        for (int j = 0; j < 4; j++)
#pragma unroll
            for (int r = 0; r < 4; r++) acc[i][j][r] = 0.f;

    const float4 zero4 = make_float4(0.f, 0.f, 0.f, 0.f);
    float4 ra[2], rb[2];

    auto store_tiles = [&](int buf) {
#pragma unroll
        for (int i = 0; i < 2; i++) {
            uint32_t h0, l0, h1, l1;
            split2(ra[i].x, ra[i].y, h0, l0);
            split2(ra[i].z, ra[i].w, h1, l1);
            int r = arow + i * 64;
            Ah[buf][aq * 2][r] = h0;     Al[buf][aq * 2][r] = l0;
            Ah[buf][aq * 2 + 1][r] = h1; Al[buf][aq * 2 + 1][r] = l1;
        }
        uint32_t h[4], l[4];
        split2(rb[0].x, rb[1].x, h[0], l[0]);
        split2(rb[0].y, rb[1].y, h[1], l[1]);
        split2(rb[0].z, rb[1].z, h[2], l[2]);
        split2(rb[0].w, rb[1].w, h[3], l[3]);
        *(uint4*)&Bh[buf][bkp][bc4] = make_uint4(h[0], h[1], h[2], h[3]);
        *(uint4*)&Bl[buf][bkp][bc4] = make_uint4(l[0], l[1], l[2], l[3]);
    };

    {
        int gr0 = bm + arow, gr1 = bm + arow + 64;
        ra[0] = (gr0 < M) ? *(const float4*)(A + (size_t)gr0 * K + aq * 4) : zero4;
        ra[1] = (gr1 < M) ? *(const float4*)(A + (size_t)gr1 * K + aq * 4) : zero4;
        rb[0] = *(const float4*)(B + (size_t)(2 * bkp) * N + bn + bc4);
        rb[1] = *(const float4*)(B + (size_t)(2 * bkp + 1) * N + bn + bc4);
        store_tiles(0);
    }
    __syncthreads();

    int nch = K / 16;
    for (int c = 0; c < nch; c++) {
        int cur = c & 1;
        if (c + 1 < nch) {
            int k0 = (c + 1) * 16;
            int gr0 = bm + arow, gr1 = bm + arow + 64;
            ra[0] = (gr0 < M) ? *(const float4*)(A + (size_t)gr0 * K + k0 + aq * 4) : zero4;
            ra[1] = (gr1 < M) ? *(const float4*)(A + (size_t)gr1 * K + k0 + aq * 4) : zero4;
            rb[0] = *(const float4*)(B + (size_t)(k0 + 2 * bkp) * N + bn + bc4);
            rb[1] = *(const float4*)(B + (size_t)(k0 + 2 * bkp + 1) * N + bn + bc4);
        }
        {
            uint32_t ahi[4][4], alo[4][4];
#pragma unroll
            for (int mi = 0; mi < 4; mi++) {
                int r = wm + mi * 16 + gid;
                ahi[mi][0] = Ah[cur][tig][r];     alo[mi][0] = Al[cur][tig][r];
                ahi[mi][1] = Ah[cur][tig][r + 8]; alo[mi][1] = Al[cur][tig][r + 8];
                ahi[mi][2] = Ah[cur][tig + 4][r];     alo[mi][2] = Al[cur][tig + 4][r];
                ahi[mi][3] = Ah[cur][tig + 4][r + 8]; alo[mi][3] = Al[cur][tig + 4][r + 8];
            }
            uint32_t bhi[4][2], blo[4][2];
#pragma unroll
            for (int ni = 0; ni < 4; ni++) {
                int cc = wn + ni * 8 + gid;
                bhi[ni][0] = Bh[cur][tig][cc];     blo[ni][0] = Bl[cur][tig][cc];
                bhi[ni][1] = Bh[cur][tig + 4][cc]; blo[ni][1] = Bl[cur][tig + 4][cc];
            }
#pragma unroll
            for (int mi = 0; mi < 4; mi++)
#pragma unroll
                for (int ni = 0; ni < 4; ni++) {
                    mma_bf16(acc[mi][ni], ahi[mi], bhi[ni]);
                    mma_bf16(acc[mi][ni], alo[mi], bhi[ni]);
                    mma_bf16(acc[mi][ni], ahi[mi], blo[ni]);
                }
        }
        if (c + 1 < nch) {
            __syncthreads();
            store_tiles(1 - cur);
            __syncthreads();
        }
    }

#pragma unroll
    for (int ni = 0; ni < 4; ni++) {
        int col = bn + wn + ni * 8 + tig * 2;
#pragma unroll
        for (int mi = 0; mi < 4; mi++) {
            int r0 = bm + wm + mi * 16 + gid;
            float2 v0 = make_float2(fmaxf(acc[mi][ni][0], 0.f), fmaxf(acc[mi][ni][1], 0.f));
            float2 v1 = make_float2(fmaxf(acc[mi][ni][2], 0.f), fmaxf(acc[mi][ni][3], 0.f));
            if (r0 < M) {
                int g = __ldg(batchmap + r0);
                red_add_v2(pool + (size_t)g * 256 + col, v0);
            }
            if (r0 + 8 < M) {
                int g = __ldg(batchmap + r0 + 8);
                red_add_v2(pool + (size_t)g * 256 + col, v1);
            }
        }
    }
}

__global__ void pred2(float* __restrict__ out) {
    int g = blockIdx.x;
    int k = threadIdx.x;
    __shared__ float p[256];
    p[k] = g_poolz[g * 256 + k];
    __syncthreads();
    if (k < NT) {
        const float* wf = g_wf + k * 256;
        float s = 0.f;
#pragma unroll 16
        for (int i = 0; i < 256; i++) s += p[i] * wf[i];
        float cnt = fmaxf((float)g_cnt[g], 1.f);
        out[g * NT + k] = s / cnt + g_bf[k];
    }
}

// ---------------- launch (single stream) --------------------------------------
extern "C" void kernel_launch(void* const* d_in, const int* in_sizes, int n_in,
                              void* d_out, int out_size) {
    const int*   x        = (const int*)  d_in[0];
    const int*   ei       = (const int*)  d_in[1];
    const float* ea       = (const float*)d_in[2];
    const int*   batch    = (const int*)  d_in[3];
    const int*   sli      = (const int*)  d_in[4];
    const int*   slt      = (const int*)  d_in[5];
    const float* node_emb = (const float*)d_in[6];
    const float* L[2][10];
    for (int l = 0; l < 2; l++)
        for (int j = 0; j < 10; j++)
            L[l][j] = (const float*)d_in[7 + l * 10 + j];
    const float* pred_w = (const float*)d_in[27];
    const float* pred_b = (const float*)d_in[28];
    float* out = (float*)d_out;

    int N = in_sizes[0];
    int E = in_sizes[1] / 2;
    int B = (N + 255) / 256;

    float *p_agg, *p_w1ext, *p_poolz;
    int *p_cnt, *p_deg;
    cudaGetSymbolAddress((void**)&p_agg,   g_agg);
    cudaGetSymbolAddress((void**)&p_w1ext, g_w1ext);
    cudaGetSymbolAddress((void**)&p_poolz, g_poolz);
    cudaGetSymbolAddress((void**)&p_cnt,   g_cnt);
    cudaGetSymbolAddress((void**)&p_deg,   g_deg);

    // zeroing via memset nodes (full-BW, graph-capturable)
    cudaMemsetAsync(p_deg,   0, (size_t)N * sizeof(int), 0);
    cudaMemsetAsync(p_poolz, 0, (size_t)NG * 2 * H * sizeof(float), 0);
    cudaMemsetAsync(p_cnt,   0, (size_t)NG * sizeof(int), 0);

    deg_count<<<(E + 255) / 256, 256>>>(ei, E);
    prep_all<<<414, 256>>>(node_emb,
                           L[0][0], L[0][1], L[0][2], L[0][3], L[0][4], L[0][5], L[0][6], L[0][7],
                           L[1][0], L[1][1], L[1][2], L[1][3], L[1][4], L[1][5], L[1][6], L[1][7],
                           L[1][8], L[1][9], pred_w, pred_b, sli, slt);
    scan1<<<B, 256>>>(batch, N);
    scan2<<<1, 256>>>(B);
    scatter<<<(E + 255) / 256, 256>>>(ei, E);
    easum_gather<<<(N * 32 + 255) / 256, 256>>>(ea, x, N, E);

    // layer 0: fused rank-13 A producer GEMM -> h1
    gemm_aff<<<(N + 127) / 128, 256>>>(x, L[0][8], L[0][9], N);

    // layer 1: gather + pooled GEMM1
    aggregate<<<(N * 32 + 255) / 256, 256>>>(N, E);
    gemm_tc<<<dim3((N + 127) / 128, 2), 256>>>(
        p_agg, p_w1ext, N, 256, KEXT, batch, p_poolz);

    pred2<<<NG, 256>>>(out);
}

// round 16
// speedup vs baseline: 1.1108x; 1.1108x over previous
#include <cuda_runtime.h>
#include <math.h>
#include <stdint.h>

#define H 128
#define KEXT 144
#define EAP 12            // easum row: 9 attrs, deg, cnt1, pad
#define NG 256
#define NT 40
#define MAXN 50048
#define MAXE 600064
#define BN_EPS 1e-5f
#define APAD 132
#define BPAD 136

// ---------------- scratch ----------------------------------------------------
__device__ float g_h[MAXN * H];
__device__ float g_agg[MAXN * KEXT];
__device__ float g_easum[MAXN * EAP];
__device__ float g_w1ext[KEXT * 2 * H];
__device__ float g_umat[13 * 2 * H];
__device__ float g_poolz[NG * 2 * H];
__device__ float g_wf[NT * 2 * H];
__device__ float g_bf[NT];
__device__ int   g_cnt[NG];
__device__ int   g_off[MAXN];       // per-block-exclusive prefix
__device__ int   g_bsum[256];       // exclusive block sums
__device__ int   g_fill[MAXN];
__device__ int   g_csrc[MAXE];

// ---------------- helpers ---------------------------------------------------
__device__ __forceinline__ void red_add_v4(float* p, float4 v) {
    asm volatile("red.global.add.v4.f32 [%0], {%1,%2,%3,%4};"
                 :: "l"(p), "f"(v.x), "f"(v.y), "f"(v.z), "f"(v.w) : "memory");
}
__device__ __forceinline__ void red_add_v2(float* p, float2 v) {
    asm volatile("red.global.add.v2.f32 [%0], {%1,%2};"
                 :: "l"(p), "f"(v.x), "f"(v.y) : "memory");
}
__device__ __forceinline__ uint32_t pack2(float lo, float hi) {
    uint32_t r;
    asm("cvt.rn.bf16x2.f32 %0, %1, %2;" : "=r"(r) : "f"(hi), "f"(lo));
    return r;
}
__device__ __forceinline__ void split2(float f0, float f1, uint32_t& hi, uint32_t& lo) {
    hi = pack2(f0, f1);
    float h0 = __uint_as_float(hi << 16);
    float h1 = __uint_as_float(hi & 0xffff0000u);
    lo = pack2(f0 - h0, f1 - h1);
}
__device__ __forceinline__ void mma_bf16(float* d, const uint32_t* a, const uint32_t* b) {
    asm volatile("mma.sync.aligned.m16n8k16.row.col.f32.bf16.bf16.f32 "
                 "{%0,%1,%2,%3},{%4,%5,%6,%7},{%8,%9},{%0,%1,%2,%3};"
                 : "+f"(d[0]), "+f"(d[1]), "+f"(d[2]), "+f"(d[3])
                 : "r"(a[0]), "r"(a[1]), "r"(a[2]), "r"(a[3]),
                   "r"(b[0]), "r"(b[1]));
}

// ---------------- setup kernels ----------------------------------------------
__global__ void edge_presum(const int* __restrict__ ei, const float* __restrict__ ea,
                            const int* __restrict__ x, int E) {
    int e = blockIdx.x * blockDim.x + threadIdx.x;
    if (e >= E) return;
    int d = __ldg(ei + e);
    int s = __ldg(ei + E + e);
    const float* a = ea + (size_t)e * 9;
    float4 v0 = make_float4(a[0], a[1], a[2], a[3]);
    float4 v1 = make_float4(a[4], a[5], a[6], a[7]);
    float4 v2 = make_float4(a[8], 1.f, (float)__ldg(x + s), 0.f);
    float* p = g_easum + (size_t)d * EAP;
    red_add_v4(p, v0);
    red_add_v4(p + 4, v1);
    red_add_v4(p + 8, v2);
}

// scan1: per-block exclusive prefix of deg + block totals; also zero g_fill and
// accumulate per-graph node counts (one thread per node).
__global__ void scan1(const int* __restrict__ batch, int N) {
    int b = blockIdx.x, t = threadIdx.x;
    int i = b * 256 + t;
    int v = (i < N) ? (int)g_easum[(size_t)i * EAP + 9] : 0;
    __shared__ int sm[256];
    sm[t] = v;
    __syncthreads();
#pragma unroll
    for (int off = 1; off < 256; off <<= 1) {
        int xx = (t >= off) ? sm[t - off] : 0;
        __syncthreads();
        sm[t] += xx;
        __syncthreads();
    }
    if (i < N) {
        g_off[i] = sm[t] - v;
        g_fill[i] = 0;
        atomicAdd(&g_cnt[batch[i]], 1);
    }
    if (t == 255) g_bsum[b] = sm[255];
}
__global__ void scan2(int B) {
    int t = threadIdx.x;
    int v = (t < B) ? g_bsum[t] : 0;
    __shared__ int sm[256];
    sm[t] = v;
    __syncthreads();
#pragma unroll
    for (int off = 1; off < 256; off <<= 1) {
        int xx = (t >= off) ? sm[t - off] : 0;
        __syncthreads();
        sm[t] += xx;
        __syncthreads();
    }
    if (t < B) g_bsum[t] = sm[t] - v;
}

__global__ void scatter(const int* __restrict__ ei, int E) {
    int e = blockIdx.x * blockDim.x + threadIdx.x;
    if (e >= E) return;
    int d = __ldg(ei + e);
    int slot = atomicAdd(&g_fill[d], 1);
    int base = __ldg(g_off + d) + __ldg(g_bsum + (d >> 8));
    g_csrc[base + slot] = __ldg(ei + E + e);
}

// ---- merged prep: blocks [0,144) w1ext | [144,157) umat | [157,414) wf/bf ---
__global__ void prep_all(const float* __restrict__ emb,
                         const float* __restrict__ enc_w0, const float* __restrict__ enc_b0,
                         const float* __restrict__ w1_0,   const float* __restrict__ b1_0,
                         const float* __restrict__ gm0,    const float* __restrict__ bt0,
                         const float* __restrict__ mn0,    const float* __restrict__ vr0,
                         const float* __restrict__ enc_w1, const float* __restrict__ enc_b1,
                         const float* __restrict__ w1_1,   const float* __restrict__ b1_1,
                         const float* __restrict__ gm1,    const float* __restrict__ bt1,
                         const float* __restrict__ mn1,    const float* __restrict__ vr1,
                         const float* __restrict__ w2_1,   const float* __restrict__ b2_1,
                         const float* __restrict__ pw,     const float* __restrict__ pb,
                         const int* __restrict__ sli_p,    const int* __restrict__ slt_p) {
    int b = blockIdx.x;
    int tid = threadIdx.x;
    if (b < 144) {
        int k = b, c = tid;
        float sc = gm1[c] * rsqrtf(vr1[c] + BN_EPS);
        float sh = (b1_1[c] - mn1[c]) * sc + bt1[c];
        if (k < 128) {
            g_w1ext[k * 256 + c] = w1_1[k * 256 + c] * sc;
        } else if (k < 139) {
            __shared__ float f[128];
            int j = k - 128;
            if (c < 128) {
                float fv;
                if (j < 9)       fv = enc_w1[j * 128 + c];
                else if (j == 9) fv = enc_b1[c];
                else             fv = (float)(*slt_p) * enc_w1[(*sli_p) * 128 + c];
                f[c] = fv;
            }
            __syncthreads();
            float s = 0.f;
            const float* wb = w1_1 + 128 * 256 + c;
#pragma unroll 16
            for (int i = 0; i < 128; i++) s += f[i] * wb[i * 256];
            g_w1ext[k * 256 + c] = s * sc + (k == 138 ? sh : 0.f);
        } else {
            g_w1ext[k * 256 + c] = 0.f;
        }
    } else if (b < 157) {
        int r = b - 144, c = tid;
        __shared__ float f[128];
        if (c < 128) {
            float fv;
            if (r < 2)        fv = emb[r * 128 + c];
            else if (r < 11)  fv = enc_w0[(r - 2) * 128 + c];
            else if (r == 11) fv = enc_b0[c];
            else              fv = (float)(*slt_p) * enc_w0[(*sli_p) * 128 + c];
            f[c] = fv;
        }
        __syncthreads();
        int base = (r < 2) ? 0 : 128;
        float s = 0.f;
        const float* wb = w1_0 + base * 256 + c;
#pragma unroll 16
        for (int i = 0; i < 128; i++) s += f[i] * wb[i * 256];
        float sc = gm0[c] * rsqrtf(vr0[c] + BN_EPS);
        float sh = (b1_0[c] - mn0[c]) * sc + bt0[c];
        g_umat[r * 256 + c] = s * sc + (r == 12 ? sh : 0.f);
    } else {
        int k = b - 157;
        __shared__ float ws[128];
        if (tid < 128) ws[tid] = (k < 256) ? w2_1[(size_t)k * 128 + tid] : b2_1[tid];
        __syncthreads();
        int w = tid >> 5, lane = tid & 31;
        float acc[5] = {0.f, 0.f, 0.f, 0.f, 0.f};
#pragma unroll
        for (int j = 0; j < 4; j++) {
            int i = j * 32 + lane;
            float wv = ws[i];
#pragma unroll
            for (int u = 0; u < 5; u++) {
                int t = w * 5 + u;
                acc[u] += wv * (__ldg(pw + i * NT + t) + __ldg(pw + (i + 128) * NT + t));
            }
        }
#pragma unroll
        for (int u = 0; u < 5; u++)
#pragma unroll
            for (int off = 16; off; off >>= 1)
                acc[u] += __shfl_down_sync(0xffffffffu, acc[u], off);
        if (lane == 0) {
#pragma unroll
            for (int u = 0; u < 5; u++) {
                int t = w * 5 + u;
                if (k < 256) g_wf[t * 256 + k] = acc[u];
                else         g_bf[t] = acc[u] + pb[t];
            }
        }
    }
}

// layer-1 neighbor gather (warp per node, 8 edges in flight)
__global__ void aggregate(int N, int E) {
    int t = blockIdx.x * blockDim.x + threadIdx.x;
    int n = t >> 5;
    if (n >= N) return;
    int lane = t & 31;
    float4 acc = *(const float4*)(g_h + (size_t)n * H + lane * 4);  // self loop
    int beg = __ldg(g_off + n) + __ldg(g_bsum + (n >> 8));
    int end = (n + 1 < N) ? (__ldg(g_off + n + 1) + __ldg(g_bsum + ((n + 1) >> 8))) : E;
    int e = beg;
    for (; e + 8 <= end; e += 8) {
        int s[8];
#pragma unroll
        for (int k = 0; k < 8; k++) s[k] = __ldg(g_csrc + e + k);
        float4 v[8];
#pragma unroll
        for (int k = 0; k < 8; k++)
            v[k] = *(const float4*)(g_h + (size_t)s[k] * H + lane * 4);
#pragma unroll
        for (int k = 0; k < 8; k++) {
            acc.x += v[k].x; acc.y += v[k].y; acc.z += v[k].z; acc.w += v[k].w;
        }
    }
    if (e + 4 <= end) {
        int s[4];
#pragma unroll
        for (int k = 0; k < 4; k++) s[k] = __ldg(g_csrc + e + k);
        float4 v[4];
#pragma unroll
        for (int k = 0; k < 4; k++)
            v[k] = *(const float4*)(g_h + (size_t)s[k] * H + lane * 4);
#pragma unroll
        for (int k = 0; k < 4; k++) {
            acc.x += v[k].x; acc.y += v[k].y; acc.z += v[k].z; acc.w += v[k].w;
        }
        e += 4;
    }
    for (; e < end; e++) {
        int s0 = __ldg(g_csrc + e);
        float4 v0 = *(const float4*)(g_h + (size_t)s0 * H + lane * 4);
        acc.x += v0.x; acc.y += v0.y; acc.z += v0.z; acc.w += v0.w;
    }
    *(float4*)(g_agg + (size_t)n * KEXT + lane * 4) = acc;
    if (lane < 4) {
        const float* s = g_easum + (size_t)n * EAP;
        float4 ex;
        if (lane == 0)      ex = make_float4(s[0], s[1], s[2], s[3]);
        else if (lane == 1) ex = make_float4(s[4], s[5], s[6], s[7]);
        else if (lane == 2) ex = make_float4(s[8], s[9] + 1.f, 1.f, 0.f);
        else                ex = make_float4(0.f, 0.f, 0.f, 0.f);
        *(float4*)(g_agg + (size_t)n * KEXT + 128 + lane * 4) = ex;
    }
}

// ---------------- GEMM0 with fused rank-13 A producer -------------------------
__global__ void __launch_bounds__(256, 2)
gemm_aff(const int* __restrict__ x, const float* __restrict__ B /*w2_0 [256,128]*/,
         const float* __restrict__ shift /*b2_0*/, int M) {
    const int N = 128, K = 256;
    __shared__ uint32_t Ah[2][8][APAD], Al[2][8][APAD];
    __shared__ uint32_t Bh[2][8][BPAD], Bl[2][8][BPAD];
    __shared__ float U[13][256];
    __shared__ float coef[128][14];
    int bm = blockIdx.x * 128;
    int tid = threadIdx.x;
    int wid = tid >> 5, lane = tid & 31;
    int gid = lane >> 2, tig = lane & 3;
    int wm = (wid >> 2) * 64, wn = (wid & 3) * 32;

    int arow = tid >> 2, aq = tid & 3;
    int bkp = tid >> 5, bc4 = (tid & 31) * 4;

    for (int idx = tid; idx < 13 * 256; idx += 256)
        U[idx >> 8][idx & 255] = g_umat[idx];
    if (tid < 128) {
        int n = bm + tid;
        if (n < M) {
            const float* s = g_easum + (size_t)n * EAP;
            float deg = s[9], cnt1 = s[10];
            int xv = __ldg(x + n);
            coef[tid][0] = deg - cnt1 + (xv == 0 ? 1.f : 0.f);
            coef[tid][1] = cnt1 + (xv == 1 ? 1.f : 0.f);
#pragma unroll
            for (int j = 0; j < 9; j++) coef[tid][2 + j] = s[j];
            coef[tid][11] = deg + 1.f;
            coef[tid][12] = 1.f;
        } else {
#pragma unroll
            for (int j = 0; j < 13; j++) coef[tid][j] = 0.f;
        }
    }

    float acc[4][4][4];
#pragma unroll
    for (int i = 0; i < 4; i++)
#pragma unroll
        for (int j = 0; j < 4; j++)
#pragma unroll
            for (int r = 0; r < 4; r++) acc[i][j][r] = 0.f;

    float4 ra[2], rb[2];
    __syncthreads();   // U/coef ready

    auto compute_a = [&](int k0) {
#pragma unroll
        for (int i = 0; i < 2; i++) {
            int r = arow + i * 64;
            float v[4];
#pragma unroll
            for (int kk = 0; kk < 4; kk++) {
                int k = k0 + aq * 4 + kk;
                float s = 0.f;
#pragma unroll
                for (int j = 0; j < 13; j++) s += coef[r][j] * U[j][k];
                v[kk] = fmaxf(s, 0.f);
            }
            ra[i] = make_float4(v[0], v[1], v[2], v[3]);
        }
    };
    auto store_tiles = [&](int buf) {
#pragma unroll
        for (int i = 0; i < 2; i++) {
            uint32_t h0, l0, h1, l1;
            split2(ra[i].x, ra[i].y, h0, l0);
            split2(ra[i].z, ra[i].w, h1, l1);
            int r = arow + i * 64;
            Ah[buf][aq * 2][r] = h0;     Al[buf][aq * 2][r] = l0;
            Ah[buf][aq * 2 + 1][r] = h1; Al[buf][aq * 2 + 1][r] = l1;
        }
        uint32_t h[4], l[4];
        split2(rb[0].x, rb[1].x, h[0], l[0]);
        split2(rb[0].y, rb[1].y, h[1], l[1]);
        split2(rb[0].z, rb[1].z, h[2], l[2]);
        split2(rb[0].w, rb[1].w, h[3], l[3]);
        *(uint4*)&Bh[buf][bkp][bc4] = make_uint4(h[0], h[1], h[2], h[3]);
        *(uint4*)&Bl[buf][bkp][bc4] = make_uint4(l[0], l[1], l[2], l[3]);
    };

    {
        rb[0] = *(const float4*)(B + (size_t)(2 * bkp) * N + bc4);
        rb[1] = *(const float4*)(B + (size_t)(2 * bkp + 1) * N + bc4);
        compute_a(0);
        store_tiles(0);
    }
    __syncthreads();

    const int nch = K / 16;
    for (int c = 0; c < nch; c++) {
        int cur = c & 1;
        if (c + 1 < nch) {
            int k0 = (c + 1) * 16;
            rb[0] = *(const float4*)(B + (size_t)(k0 + 2 * bkp) * N + bc4);
            rb[1] = *(const float4*)(B + (size_t)(k0 + 2 * bkp + 1) * N + bc4);
        }
        {
            uint32_t ahi[4][4], alo[4][4];
#pragma unroll
            for (int mi = 0; mi < 4; mi++) {
                int r = wm + mi * 16 + gid;
                ahi[mi][0] = Ah[cur][tig][r];     alo[mi][0] = Al[cur][tig][r];
                ahi[mi][1] = Ah[cur][tig][r + 8]; alo[mi][1] = Al[cur][tig][r + 8];
                ahi[mi][2] = Ah[cur][tig + 4][r];     alo[mi][2] = Al[cur][tig + 4][r];
                ahi[mi][3] = Ah[cur][tig + 4][r + 8]; alo[mi][3] = Al[cur][tig + 4][r + 8];
            }
            uint32_t bhi[4][2], blo[4][2];
#pragma unroll
            for (int ni = 0; ni < 4; ni++) {
                int cc = wn + ni * 8 + gid;
                bhi[ni][0] = Bh[cur][tig][cc];     blo[ni][0] = Bl[cur][tig][cc];
                bhi[ni][1] = Bh[cur][tig + 4][cc]; blo[ni][1] = Bl[cur][tig + 4][cc];
            }
#pragma unroll
            for (int mi = 0; mi < 4; mi++)
#pragma unroll
                for (int ni = 0; ni < 4; ni++) {
                    mma_bf16(acc[mi][ni], ahi[mi], bhi[ni]);
                    mma_bf16(acc[mi][ni], alo[mi], bhi[ni]);
                    mma_bf16(acc[mi][ni], ahi[mi], blo[ni]);
                }
        }
        if (c + 1 < nch) {
            compute_a((c + 1) * 16);
            __syncthreads();
            store_tiles(1 - cur);
            __syncthreads();
        }
    }

#pragma unroll
    for (int ni = 0; ni < 4; ni++) {
        int col = wn + ni * 8 + tig * 2;
        float t0 = __ldg(shift + col), t1 = __ldg(shift + col + 1);
#pragma unroll
        for (int mi = 0; mi < 4; mi++) {
            int r0 = bm + wm + mi * 16 + gid;
            float2 v0 = make_float2(fmaxf(acc[mi][ni][0] + t0, 0.f), fmaxf(acc[mi][ni][1] + t1, 0.f));
            float2 v1 = make_float2(fmaxf(acc[mi][ni][2] + t0, 0.f), fmaxf(acc[mi][ni][3] + t1, 0.f));
            if (r0 < M)     *(float2*)(g_h + (size_t)r0 * N + col) = v0;
            if (r0 + 8 < M) *(float2*)(g_h + (size_t)(r0 + 8) * N + col) = v1;
        }
    }
}

// ---------------- pooled GEMM1 (bf16 hi/lo split, red.v2 epilogue) ------------
__global__ void __launch_bounds__(256, 2)
gemm_tc(const float* __restrict__ A, const float* __restrict__ B,
        int M, int N, int K,
        const int* __restrict__ batchmap, float* __restrict__ pool) {
    __shared__ uint32_t Ah[2][8][APAD], Al[2][8][APAD];
    __shared__ uint32_t Bh[2][8][BPAD], Bl[2][8][BPAD];
    int bm = blockIdx.x * 128, bn = blockIdx.y * 128;
    int tid = threadIdx.x;
    int wid = tid >> 5, lane = tid & 31;
    int gid = lane >> 2, tig = lane & 3;
    int wm = (wid >> 2) * 64, wn = (wid & 3) * 32;

    int arow = tid >> 2, aq = tid & 3;
    int bkp = tid >> 5, bc4 = (tid & 31) * 4;

    float acc[4][4][4];
#pragma unroll
    for (int i = 0; i < 4; i++)
#pragma unroll
        for (int j = 0; j < 4; j++)
#pragma unroll
            for (int r = 0; r < 4; r++) acc[i][j][r] = 0.f;

    const float4 zero4 = make_float4(0.f, 0.f, 0.f, 0.f);
    float4 ra[2], rb[2];

    auto store_tiles = [&](int buf) {
#pragma unroll
        for (int i = 0; i < 2; i++) {
            uint32_t h0, l0, h1, l1;
            split2(ra[i].x, ra[i].y, h0, l0);
            split2(ra[i].z, ra[i].w, h1, l1);
            int r = arow + i * 64;
            Ah[buf][aq * 2][r] = h0;     Al[buf][aq * 2][r] = l0;
            Ah[buf][aq * 2 + 1][r] = h1; Al[buf][aq * 2 + 1][r] = l1;
        }
        uint32_t h[4], l[4];
        split2(rb[0].x, rb[1].x, h[0], l[0]);
        split2(rb[0].y, rb[1].y, h[1], l[1]);
        split2(rb[0].z, rb[1].z, h[2], l[2]);
        split2(rb[0].w, rb[1].w, h[3], l[3]);
        *(uint4*)&Bh[buf][bkp][bc4] = make_uint4(h[0], h[1], h[2], h[3]);
        *(uint4*)&Bl[buf][bkp][bc4] = make_uint4(l[0], l[1], l[2], l[3]);
    };

    {
        int gr0 = bm + arow, gr1 = bm + arow + 64;
        ra[0] = (gr0 < M) ? *(const float4*)(A + (size_t)gr0 * K + aq * 4) : zero4;
        ra[1] = (gr1 < M) ? *(const float4*)(A + (size_t)gr1 * K + aq * 4) : zero4;
        rb[0] = *(const float4*)(B + (size_t)(2 * bkp) * N + bn + bc4);
        rb[1] = *(const float4*)(B + (size_t)(2 * bkp + 1) * N + bn + bc4);
        store_tiles(0);
    }
    __syncthreads();

    int nch = K / 16;
    for (int c = 0; c < nch; c++) {
        int cur = c & 1;
        if (c + 1 < nch) {
            int k0 = (c + 1) * 16;
            int gr0 = bm + arow, gr1 = bm + arow + 64;
            ra[0] = (gr0 < M) ? *(const float4*)(A + (size_t)gr0 * K + k0 + aq * 4) : zero4;
            ra[1] = (gr1 < M) ? *(const float4*)(A + (size_t)gr1 * K + k0 + aq * 4) : zero4;
            rb[0] = *(const float4*)(B + (size_t)(k0 + 2 * bkp) * N + bn + bc4);
            rb[1] = *(const float4*)(B + (size_t)(k0 + 2 * bkp + 1) * N + bn + bc4);
        }
        {
            uint32_t ahi[4][4], alo[4][4];
#pragma unroll
            for (int mi = 0; mi < 4; mi++) {
                int r = wm + mi * 16 + gid;
                ahi[mi][0] = Ah[cur][tig][r];     alo[mi][0] = Al[cur][tig][r];
                ahi[mi][1] = Ah[cur][tig][r + 8]; alo[mi][1] = Al[cur][tig][r + 8];
                ahi[mi][2] = Ah[cur][tig + 4][r];     alo[mi][2] = Al[cur][tig + 4][r];
                ahi[mi][3] = Ah[cur][tig + 4][r + 8]; alo[mi][3] = Al[cur][tig + 4][r + 8];
            }
            uint32_t bhi[4][2], blo[4][2];
#pragma unroll
            for (int ni = 0; ni < 4; ni++) {
                int cc = wn + ni * 8 + gid;
                bhi[ni][0] = Bh[cur][tig][cc];     blo[ni][0] = Bl[cur][tig][cc];
                bhi[ni][1] = Bh[cur][tig + 4][cc]; blo[ni][1] = Bl[cur][tig + 4][cc];
            }
#pragma unroll
            for (int mi = 0; mi < 4; mi++)
#pragma unroll
                for (int ni = 0; ni < 4; ni++) {
                    mma_bf16(acc[mi][ni], ahi[mi], bhi[ni]);
                    mma_bf16(acc[mi][ni], alo[mi], bhi[ni]);
                    mma_bf16(acc[mi][ni], ahi[mi], blo[ni]);
                }
        }
        if (c + 1 < nch) {
            __syncthreads();
            store_tiles(1 - cur);
            __syncthreads();
        }
    }

#pragma unroll
    for (int ni = 0; ni < 4; ni++) {
        int col = bn + wn + ni * 8 + tig * 2;
#pragma unroll
        for (int mi = 0; mi < 4; mi++) {
            int r0 = bm + wm + mi * 16 + gid;
            float2 v0 = make_float2(fmaxf(acc[mi][ni][0], 0.f), fmaxf(acc[mi][ni][1], 0.f));
            float2 v1 = make_float2(fmaxf(acc[mi][ni][2], 0.f), fmaxf(acc[mi][ni][3], 0.f));
            if (r0 < M) {
                int g = __ldg(batchmap + r0);
                red_add_v2(pool + (size_t)g * 256 + col, v0);
            }
            if (r0 + 8 < M) {
                int g = __ldg(batchmap + r0 + 8);
                red_add_v2(pool + (size_t)g * 256 + col, v1);
            }
        }
    }
}

__global__ void pred2(float* __restrict__ out) {
    int g = blockIdx.x;
    int k = threadIdx.x;
    __shared__ float p[256];
    p[k] = g_poolz[g * 256 + k];
    __syncthreads();
    if (k < NT) {
        const float* wf = g_wf + k * 256;
        float s = 0.f;
#pragma unroll 16
        for (int i = 0; i < 256; i++) s += p[i] * wf[i];
        float cnt = fmaxf((float)g_cnt[g], 1.f);
        out[g * NT + k] = s / cnt + g_bf[k];
    }
}

// ---------------- launch (single stream, memset-based zeroing) ----------------
extern "C" void kernel_launch(void* const* d_in, const int* in_sizes, int n_in,
                              void* d_out, int out_size) {
    const int*   x        = (const int*)  d_in[0];
    const int*   ei       = (const int*)  d_in[1];
    const float* ea       = (const float*)d_in[2];
    const int*   batch    = (const int*)  d_in[3];
    const int*   sli      = (const int*)  d_in[4];
    const int*   slt      = (const int*)  d_in[5];
    const float* node_emb = (const float*)d_in[6];
    const float* L[2][10];
    for (int l = 0; l < 2; l++)
        for (int j = 0; j < 10; j++)
            L[l][j] = (const float*)d_in[7 + l * 10 + j];
    const float* pred_w = (const float*)d_in[27];
    const float* pred_b = (const float*)d_in[28];
    float* out = (float*)d_out;

    int N = in_sizes[0];
    int E = in_sizes[1] / 2;
    int B = (N + 255) / 256;

    float *p_agg, *p_w1ext, *p_poolz, *p_easum;
    int *p_cnt;
    cudaGetSymbolAddress((void**)&p_agg,   g_agg);
    cudaGetSymbolAddress((void**)&p_w1ext, g_w1ext);
    cudaGetSymbolAddress((void**)&p_poolz, g_poolz);
    cudaGetSymbolAddress((void**)&p_easum, g_easum);
    cudaGetSymbolAddress((void**)&p_cnt,   g_cnt);

    // zeroing via memset nodes (full-BW, graph-capturable)
    cudaMemsetAsync(p_easum, 0, (size_t)N * EAP * sizeof(float), 0);
    cudaMemsetAsync(p_poolz, 0, (size_t)NG * 2 * H * sizeof(float), 0);
    cudaMemsetAsync(p_cnt,   0, (size_t)NG * sizeof(int), 0);

    edge_presum<<<(E + 255) / 256, 256>>>(ei, ea, x, E);
    prep_all<<<414, 256>>>(node_emb,
                           L[0][0], L[0][1], L[0][2], L[0][3], L[0][4], L[0][5], L[0][6], L[0][7],
                           L[1][0], L[1][1], L[1][2], L[1][3], L[1][4], L[1][5], L[1][6], L[1][7],
                           L[1][8], L[1][9], pred_w, pred_b, sli, slt);
    scan1<<<B, 256>>>(batch, N);
    scan2<<<1, 256>>>(B);
    scatter<<<(E + 255) / 256, 256>>>(ei, E);

    // layer 0: fused rank-13 A producer GEMM -> h1 (z0 never materialized)
    gemm_aff<<<(N + 127) / 128, 256>>>(x, L[0][8], L[0][9], N);

    // layer 1: gather + pooled GEMM1
    aggregate<<<(N * 32 + 255) / 256, 256>>>(N, E);
    gemm_tc<<<dim3((N + 127) / 128, 2), 256>>>(
        p_agg, p_w1ext, N, 256, KEXT, batch, p_poolz);

    pred2<<<NG, 256>>>(out);
}

// round 17
// speedup vs baseline: 1.1832x; 1.0652x over previous
#include <cuda_runtime.h>
#include <math.h>
#include <stdint.h>

#define H 128
#define KEXT 144
#define EAP 12            // easum row: 9 attrs, deg, cnt1, pad
#define NG 256
#define NT 40
#define MAXN 50048
#define MAXE 600064
#define BN_EPS 1e-5f
#define APAD 132
#define BPAD 136

// ---------------- scratch ----------------------------------------------------
__device__ float g_h[MAXN * H];
__device__ float g_agg[MAXN * KEXT];
__device__ float g_easum[MAXN * EAP];
__device__ float g_w1ext[KEXT * 2 * H];
__device__ float g_umat[13 * 2 * H];
__device__ float g_poolz[NG * 2 * H];
__device__ float g_wf[NT * 2 * H];
__device__ float g_bf[NT];
__device__ int   g_cnt[NG];
__device__ int   g_off[MAXN];       // per-block-exclusive prefix
__device__ int   g_bsum[256];       // exclusive block sums
__device__ int   g_fill[MAXN];
__device__ int   g_csrc[MAXE];

// ---------------- helpers ---------------------------------------------------
__device__ __forceinline__ void red_add_v4(float* p, float4 v) {
    asm volatile("red.global.add.v4.f32 [%0], {%1,%2,%3,%4};"
                 :: "l"(p), "f"(v.x), "f"(v.y), "f"(v.z), "f"(v.w) : "memory");
}
__device__ __forceinline__ void red_add_v2(float* p, float2 v) {
    asm volatile("red.global.add.v2.f32 [%0], {%1,%2};"
                 :: "l"(p), "f"(v.x), "f"(v.y) : "memory");
}
__device__ __forceinline__ uint32_t pack2(float lo, float hi) {
    uint32_t r;
    asm("cvt.rn.bf16x2.f32 %0, %1, %2;" : "=r"(r) : "f"(hi), "f"(lo));
    return r;
}
__device__ __forceinline__ void split2(float f0, float f1, uint32_t& hi, uint32_t& lo) {
    hi = pack2(f0, f1);
    float h0 = __uint_as_float(hi << 16);
    float h1 = __uint_as_float(hi & 0xffff0000u);
    lo = pack2(f0 - h0, f1 - h1);
}
__device__ __forceinline__ void mma_bf16(float* d, const uint32_t* a, const uint32_t* b) {
    asm volatile("mma.sync.aligned.m16n8k16.row.col.f32.bf16.bf16.f32 "
                 "{%0,%1,%2,%3},{%4,%5,%6,%7},{%8,%9},{%0,%1,%2,%3};"
                 : "+f"(d[0]), "+f"(d[1]), "+f"(d[2]), "+f"(d[3])
                 : "r"(a[0]), "r"(a[1]), "r"(a[2]), "r"(a[3]),
                   "r"(b[0]), "r"(b[1]));
}

// ---------------- front: edge_presum blocks ++ prep_all blocks ----------------
// blocks [0, EB): edge_presum | [EB, EB+414): prep_all (independent work)
__global__ void front(const int* __restrict__ ei, const float* __restrict__ ea,
                      const int* __restrict__ x, int E,
                      const float* __restrict__ emb,
                      const float* __restrict__ enc_w0, const float* __restrict__ enc_b0,
                      const float* __restrict__ w1_0,   const float* __restrict__ b1_0,
                      const float* __restrict__ gm0,    const float* __restrict__ bt0,
                      const float* __restrict__ mn0,    const float* __restrict__ vr0,
                      const float* __restrict__ enc_w1, const float* __restrict__ enc_b1,
                      const float* __restrict__ w1_1,   const float* __restrict__ b1_1,
                      const float* __restrict__ gm1,    const float* __restrict__ bt1,
                      const float* __restrict__ mn1,    const float* __restrict__ vr1,
                      const float* __restrict__ w2_1,   const float* __restrict__ b2_1,
                      const float* __restrict__ pw,     const float* __restrict__ pb,
                      const int* __restrict__ sli_p,    const int* __restrict__ slt_p) {
    int EB = (int)gridDim.x - 414;
    int tid = threadIdx.x;
    if ((int)blockIdx.x < EB) {
        // ---- edge_presum ----
        int e = blockIdx.x * 256 + tid;
        if (e >= E) return;
        int d = __ldg(ei + e);
        int s = __ldg(ei + E + e);
        const float* a = ea + (size_t)e * 9;
        float4 v0 = make_float4(a[0], a[1], a[2], a[3]);
        float4 v1 = make_float4(a[4], a[5], a[6], a[7]);
        float4 v2 = make_float4(a[8], 1.f, (float)__ldg(x + s), 0.f);
        float* p = g_easum + (size_t)d * EAP;
        red_add_v4(p, v0);
        red_add_v4(p + 4, v1);
        red_add_v4(p + 8, v2);
        return;
    }
    int b = blockIdx.x - EB;
    if (b < 144) {                       // ---- layer-1 w1ext (BN folded) ----
        int k = b, c = tid;
        float sc = gm1[c] * rsqrtf(vr1[c] + BN_EPS);
        float sh = (b1_1[c] - mn1[c]) * sc + bt1[c];
        if (k < 128) {
            g_w1ext[k * 256 + c] = w1_1[k * 256 + c] * sc;
        } else if (k < 139) {
            __shared__ float f[128];
            int j = k - 128;
            if (c < 128) {
                float fv;
                if (j < 9)       fv = enc_w1[j * 128 + c];
                else if (j == 9) fv = enc_b1[c];
                else             fv = (float)(*slt_p) * enc_w1[(*sli_p) * 128 + c];
                f[c] = fv;
            }
            __syncthreads();
            float s = 0.f;
            const float* wb = w1_1 + 128 * 256 + c;
#pragma unroll 16
            for (int i = 0; i < 128; i++) s += f[i] * wb[i * 256];
            g_w1ext[k * 256 + c] = s * sc + (k == 138 ? sh : 0.f);
        } else {
            g_w1ext[k * 256 + c] = 0.f;
        }
    } else if (b < 157) {                // ---- layer-0 rank-13 basis ----
        int r = b - 144, c = tid;
        __shared__ float f2[128];
        if (c < 128) {
            float fv;
            if (r < 2)        fv = emb[r * 128 + c];
            else if (r < 11)  fv = enc_w0[(r - 2) * 128 + c];
            else if (r == 11) fv = enc_b0[c];
            else              fv = (float)(*slt_p) * enc_w0[(*sli_p) * 128 + c];
            f2[c] = fv;
        }
        __syncthreads();
        int base = (r < 2) ? 0 : 128;
        float s = 0.f;
        const float* wb = w1_0 + base * 256 + c;
#pragma unroll 16
        for (int i = 0; i < 128; i++) s += f2[i] * wb[i * 256];
        float sc = gm0[c] * rsqrtf(vr0[c] + BN_EPS);
        float sh = (b1_0[c] - mn0[c]) * sc + bt0[c];
        g_umat[r * 256 + c] = s * sc + (r == 12 ? sh : 0.f);
    } else {                             // ---- wf / bf fold ----
        int k = b - 157;
        __shared__ float ws[128];
        if (tid < 128) ws[tid] = (k < 256) ? w2_1[(size_t)k * 128 + tid] : b2_1[tid];
        __syncthreads();
        int w = tid >> 5, lane = tid & 31;
        float acc[5] = {0.f, 0.f, 0.f, 0.f, 0.f};
#pragma unroll
        for (int j = 0; j < 4; j++) {
            int i = j * 32 + lane;
            float wv = ws[i];
#pragma unroll
            for (int u = 0; u < 5; u++) {
                int t = w * 5 + u;
                acc[u] += wv * (__ldg(pw + i * NT + t) + __ldg(pw + (i + 128) * NT + t));
            }
        }
#pragma unroll
        for (int u = 0; u < 5; u++)
#pragma unroll
            for (int off = 16; off; off >>= 1)
                acc[u] += __shfl_down_sync(0xffffffffu, acc[u], off);
        if (lane == 0) {
#pragma unroll
            for (int u = 0; u < 5; u++) {
                int t = w * 5 + u;
                if (k < 256) g_wf[t * 256 + k] = acc[u];
                else         g_bf[t] = acc[u] + pb[t];
            }
        }
    }
}

__global__ void scan2(int B) {
    int t = threadIdx.x;
    int v = (t < B) ? g_bsum[t] : 0;
    __shared__ int sm[256];
    sm[t] = v;
    __syncthreads();
#pragma unroll
    for (int off = 1; off < 256; off <<= 1) {
        int xx = (t >= off) ? sm[t - off] : 0;
        __syncthreads();
        sm[t] += xx;
        __syncthreads();
    }
    if (t < B) g_bsum[t] = sm[t] - v;
}

__global__ void scatter(const int* __restrict__ ei, int E) {
    int e = blockIdx.x * blockDim.x + threadIdx.x;
    if (e >= E) return;
    int d = __ldg(ei + e);
    int slot = atomicAdd(&g_fill[d], 1);
    int base = __ldg(g_off + d) + __ldg(g_bsum + (d >> 8));
    g_csrc[base + slot] = __ldg(ei + E + e);
}

// ---------------- gemm_aff blocks ++ scan1 blocks ------------------------------
// blocks [0, GA): GEMM0 with fused rank-13 A producer (h1 = relu(relu(coef@U)@w2+b2))
// blocks [GA, GA+B): scan1 (per-block prefix of deg + fill/cnt init) — independent
__global__ void __launch_bounds__(256, 2)
gaff_scan(const int* __restrict__ x, const float* __restrict__ B_ /*w2_0*/,
          const float* __restrict__ shift /*b2_0*/, const int* __restrict__ batch,
          int M) {
    const int N = 128, K = 256;
    __shared__ uint32_t Ah[2][8][APAD], Al[2][8][APAD];
    __shared__ uint32_t Bh[2][8][BPAD], Bl[2][8][BPAD];
    __shared__ float U[13][256];
    __shared__ float coef[128][14];
    int nb = (M + 255) >> 8;            // scan1 block count
    int GA = (int)gridDim.x - nb;
    int tid = threadIdx.x;

    if ((int)blockIdx.x >= GA) {
        // ---- scan1 body ----
        int b = blockIdx.x - GA, t = tid;
        int i = b * 256 + t;
        int v = (i < M) ? (int)g_easum[(size_t)i * EAP + 9] : 0;
        int* sm = (int*)coef;           // reuse smem
        sm[t] = v;
        __syncthreads();
#pragma unroll
        for (int off = 1; off < 256; off <<= 1) {
            int xx = (t >= off) ? sm[t - off] : 0;
            __syncthreads();
            sm[t] += xx;
            __syncthreads();
        }
        if (i < M) {
            g_off[i] = sm[t] - v;
            g_fill[i] = 0;
            atomicAdd(&g_cnt[batch[i]], 1);
        }
        if (t == 255) g_bsum[b] = sm[255];
        return;
    }

    // ---- gemm_aff body ----
    int bm = blockIdx.x * 128;
    int wid = tid >> 5, lane = tid & 31;
    int gid = lane >> 2, tig = lane & 3;
    int wm = (wid >> 2) * 64, wn = (wid & 3) * 32;

    int arow = tid >> 2, aq = tid & 3;
    int bkp = tid >> 5, bc4 = (tid & 31) * 4;

    for (int idx = tid; idx < 13 * 256; idx += 256)
        U[idx >> 8][idx & 255] = g_umat[idx];
    if (tid < 128) {
        int n = bm + tid;
        if (n < M) {
            const float* s = g_easum + (size_t)n * EAP;
            float deg = s[9], cnt1 = s[10];
            int xv = __ldg(x + n);
            coef[tid][0] = deg - cnt1 + (xv == 0 ? 1.f : 0.f);
            coef[tid][1] = cnt1 + (xv == 1 ? 1.f : 0.f);
#pragma unroll
            for (int j = 0; j < 9; j++) coef[tid][2 + j] = s[j];
            coef[tid][11] = deg + 1.f;
            coef[tid][12] = 1.f;
        } else {
#pragma unroll
            for (int j = 0; j < 13; j++) coef[tid][j] = 0.f;
        }
    }

    float acc[4][4][4];
#pragma unroll
    for (int i = 0; i < 4; i++)
#pragma unroll
        for (int j = 0; j < 4; j++)
#pragma unroll
            for (int r = 0; r < 4; r++) acc[i][j][r] = 0.f;

    float4 ra[2], rb[2];
    __syncthreads();   // U/coef ready

    auto compute_a = [&](int k0) {
#pragma unroll
        for (int i = 0; i < 2; i++) {
            int r = arow + i * 64;
            float v[4];
#pragma unroll
            for (int kk = 0; kk < 4; kk++) {
                int k = k0 + aq * 4 + kk;
                float s = 0.f;
#pragma unroll
                for (int j = 0; j < 13; j++) s += coef[r][j] * U[j][k];
                v[kk] = fmaxf(s, 0.f);
            }
            ra[i] = make_float4(v[0], v[1], v[2], v[3]);
        }
    };
    auto store_tiles = [&](int buf) {
#pragma unroll
        for (int i = 0; i < 2; i++) {
            uint32_t h0, l0, h1, l1;
            split2(ra[i].x, ra[i].y, h0, l0);
            split2(ra[i].z, ra[i].w, h1, l1);
            int r = arow + i * 64;
            Ah[buf][aq * 2][r] = h0;     Al[buf][aq * 2][r] = l0;
            Ah[buf][aq * 2 + 1][r] = h1; Al[buf][aq * 2 + 1][r] = l1;
        }
        uint32_t h[4], l[4];
        split2(rb[0].x, rb[1].x, h[0], l[0]);
        split2(rb[0].y, rb[1].y, h[1], l[1]);
        split2(rb[0].z, rb[1].z, h[2], l[2]);
        split2(rb[0].w, rb[1].w, h[3], l[3]);
        *(uint4*)&Bh[buf][bkp][bc4] = make_uint4(h[0], h[1], h[2], h[3]);
        *(uint4*)&Bl[buf][bkp][bc4] = make_uint4(l[0], l[1], l[2], l[3]);
    };

    {
        rb[0] = *(const float4*)(B_ + (size_t)(2 * bkp) * N + bc4);
        rb[1] = *(const float4*)(B_ + (size_t)(2 * bkp + 1) * N + bc4);
        compute_a(0);
        store_tiles(0);
    }
    __syncthreads();

    const int nch = K / 16;
    for (int c = 0; c < nch; c++) {
        int cur = c & 1;
        if (c + 1 < nch) {
            int k0 = (c + 1) * 16;
            rb[0] = *(const float4*)(B_ + (size_t)(k0 + 2 * bkp) * N + bc4);
            rb[1] = *(const float4*)(B_ + (size_t)(k0 + 2 * bkp + 1) * N + bc4);
        }
        {
            uint32_t ahi[4][4], alo[4][4];
#pragma unroll
            for (int mi = 0; mi < 4; mi++) {
                int r = wm + mi * 16 + gid;
                ahi[mi][0] = Ah[cur][tig][r];     alo[mi][0] = Al[cur][tig][r];
                ahi[mi][1] = Ah[cur][tig][r + 8]; alo[mi][1] = Al[cur][tig][r + 8];
                ahi[mi][2] = Ah[cur][tig + 4][r];     alo[mi][2] = Al[cur][tig + 4][r];
                ahi[mi][3] = Ah[cur][tig + 4][r + 8]; alo[mi][3] = Al[cur][tig + 4][r + 8];
            }
            uint32_t bhi[4][2], blo[4][2];
#pragma unroll
            for (int ni = 0; ni < 4; ni++) {
                int cc = wn + ni * 8 + gid;
                bhi[ni][0] = Bh[cur][tig][cc];     blo[ni][0] = Bl[cur][tig][cc];
                bhi[ni][1] = Bh[cur][tig + 4][cc]; blo[ni][1] = Bl[cur][tig + 4][cc];
            }
#pragma unroll
            for (int mi = 0; mi < 4; mi++)
#pragma unroll
                for (int ni = 0; ni < 4; ni++) {
                    mma_bf16(acc[mi][ni], ahi[mi], bhi[ni]);
                    mma_bf16(acc[mi][ni], alo[mi], bhi[ni]);
                    mma_bf16(acc[mi][ni], ahi[mi], blo[ni]);
                }
        }
        if (c + 1 < nch) {
            compute_a((c + 1) * 16);
            __syncthreads();
            store_tiles(1 - cur);
            __syncthreads();
        }
    }

#pragma unroll
    for (int ni = 0; ni < 4; ni++) {
        int col = wn + ni * 8 + tig * 2;
        float t0 = __ldg(shift + col), t1 = __ldg(shift + col + 1);
#pragma unroll
        for (int mi = 0; mi < 4; mi++) {
            int r0 = bm + wm + mi * 16 + gid;
            float2 v0 = make_float2(fmaxf(acc[mi][ni][0] + t0, 0.f), fmaxf(acc[mi][ni][1] + t1, 0.f));
            float2 v1 = make_float2(fmaxf(acc[mi][ni][2] + t0, 0.f), fmaxf(acc[mi][ni][3] + t1, 0.f));
            if (r0 < M)     *(float2*)(g_h + (size_t)r0 * N + col) = v0;
            if (r0 + 8 < M) *(float2*)(g_h + (size_t)(r0 + 8) * N + col) = v1;
        }
    }
}

// layer-1 neighbor gather (warp per node, 8 edges in flight)
__global__ void aggregate(int N, int E) {
    int t = blockIdx.x * blockDim.x + threadIdx.x;
    int n = t >> 5;
    if (n >= N) return;
    int lane = t & 31;
    float4 acc = *(const float4*)(g_h + (size_t)n * H + lane * 4);  // self loop
    int beg = __ldg(g_off + n) + __ldg(g_bsum + (n >> 8));
    int end = (n + 1 < N) ? (__ldg(g_off + n + 1) + __ldg(g_bsum + ((n + 1) >> 8))) : E;
    int e = beg;
    for (; e + 8 <= end; e += 8) {
        int s[8];
#pragma unroll
        for (int k = 0; k < 8; k++) s[k] = __ldg(g_csrc + e + k);
        float4 v[8];
#pragma unroll
        for (int k = 0; k < 8; k++)
            v[k] = *(const float4*)(g_h + (size_t)s[k] * H + lane * 4);
#pragma unroll
        for (int k = 0; k < 8; k++) {
            acc.x += v[k].x; acc.y += v[k].y; acc.z += v[k].z; acc.w += v[k].w;
        }
    }
    if (e + 4 <= end) {
        int s[4];
#pragma unroll
        for (int k = 0; k < 4; k++) s[k] = __ldg(g_csrc + e + k);
        float4 v[4];
#pragma unroll
        for (int k = 0; k < 4; k++)
            v[k] = *(const float4*)(g_h + (size_t)s[k] * H + lane * 4);
#pragma unroll
        for (int k = 0; k < 4; k++) {
            acc.x += v[k].x; acc.y += v[k].y; acc.z += v[k].z; acc.w += v[k].w;
        }
        e += 4;
    }
    for (; e < end; e++) {
        int s0 = __ldg(g_csrc + e);
        float4 v0 = *(const float4*)(g_h + (size_t)s0 * H + lane * 4);
        acc.x += v0.x; acc.y += v0.y; acc.z += v0.z; acc.w += v0.w;
    }
    *(float4*)(g_agg + (size_t)n * KEXT + lane * 4) = acc;
    if (lane < 4) {
        const float* s = g_easum + (size_t)n * EAP;
        float4 ex;
        if (lane == 0)      ex = make_float4(s[0], s[1], s[2], s[3]);
        else if (lane == 1) ex = make_float4(s[4], s[5], s[6], s[7]);
        else if (lane == 2) ex = make_float4(s[8], s[9] + 1.f, 1.f, 0.f);
        else                ex = make_float4(0.f, 0.f, 0.f, 0.f);
        *(float4*)(g_agg + (size_t)n * KEXT + 128 + lane * 4) = ex;
    }
}

// ---------------- pooled GEMM1 (bf16 hi/lo split, red.v2 epilogue) ------------
__global__ void __launch_bounds__(256, 2)
gemm_tc(const float* __restrict__ A, const float* __restrict__ B,
        int M, int N, int K,
        const int* __restrict__ batchmap, float* __restrict__ pool) {
    __shared__ uint32_t Ah[2][8][APAD], Al[2][8][APAD];
    __shared__ uint32_t Bh[2][8][BPAD], Bl[2][8][BPAD];
    int bm = blockIdx.x * 128, bn = blockIdx.y * 128;
    int tid = threadIdx.x;
    int wid = tid >> 5, lane = tid & 31;
    int gid = lane >> 2, tig = lane & 3;
    int wm = (wid >> 2) * 64, wn = (wid & 3) * 32;

    int arow = tid >> 2, aq = tid & 3;
    int bkp = tid >> 5, bc4 = (tid & 31) * 4;

    float acc[4][4][4];
#pragma unroll
    for (int i = 0; i < 4; i++)
#pragma unroll
        for (int j = 0; j < 4; j++)
#pragma unroll
            for (int r = 0; r < 4; r++) acc[i][j][r] = 0.f;

    const float4 zero4 = make_float4(0.f, 0.f, 0.f, 0.f);
    float4 ra[2], rb[2];

    auto store_tiles = [&](int buf) {
#pragma unroll
        for (int i = 0; i < 2; i++) {
            uint32_t h0, l0, h1, l1;
            split2(ra[i].x, ra[i].y, h0, l0);
            split2(ra[i].z, ra[i].w, h1, l1);
            int r = arow + i * 64;
            Ah[buf][aq * 2][r] = h0;     Al[buf][aq * 2][r] = l0;
            Ah[buf][aq * 2 + 1][r] = h1; Al[buf][aq * 2 + 1][r] = l1;
        }
        uint32_t h[4], l[4];
        split2(rb[0].x, rb[1].x, h[0], l[0]);
        split2(rb[0].y, rb[1].y, h[1], l[1]);
        split2(rb[0].z, rb[1].z, h[2], l[2]);
        split2(rb[0].w, rb[1].w, h[3], l[3]);
        *(uint4*)&Bh[buf][bkp][bc4] = make_uint4(h[0], h[1], h[2], h[3]);
        *(uint4*)&Bl[buf][bkp][bc4] = make_uint4(l[0], l[1], l[2], l[3]);
    };

    {
        int gr0 = bm + arow, gr1 = bm + arow + 64;
        ra[0] = (gr0 < M) ? *(const float4*)(A + (size_t)gr0 * K + aq * 4) : zero4;
        ra[1] = (gr1 < M) ? *(const float4*)(A + (size_t)gr1 * K + aq * 4) : zero4;
        rb[0] = *(const float4*)(B + (size_t)(2 * bkp) * N + bn + bc4);
        rb[1] = *(const float4*)(B + (size_t)(2 * bkp + 1) * N + bn + bc4);
        store_tiles(0);
    }
    __syncthreads();

    int nch = K / 16;
    for (int c = 0; c < nch; c++) {
        int cur = c & 1;
        if (c + 1 < nch) {
            int k0 = (c + 1) * 16;
            int gr0 = bm + arow, gr1 = bm + arow + 64;
            ra[0] = (gr0 < M) ? *(const float4*)(A + (size_t)gr0 * K + k0 + aq * 4) : zero4;
            ra[1] = (gr1 < M) ? *(const float4*)(A + (size_t)gr1 * K + k0 + aq * 4) : zero4;
            rb[0] = *(const float4*)(B + (size_t)(k0 + 2 * bkp) * N + bn + bc4);
            rb[1] = *(const float4*)(B + (size_t)(k0 + 2 * bkp + 1) * N + bn + bc4);
        }
        {
            uint32_t ahi[4][4], alo[4][4];
#pragma unroll
            for (int mi = 0; mi < 4; mi++) {
                int r = wm + mi * 16 + gid;
                ahi[mi][0] = Ah[cur][tig][r];     alo[mi][0] = Al[cur][tig][r];
                ahi[mi][1] = Ah[cur][tig][r + 8]; alo[mi][1] = Al[cur][tig][r + 8];
                ahi[mi][2] = Ah[cur][tig + 4][r];     alo[mi][2] = Al[cur][tig + 4][r];
                ahi[mi][3] = Ah[cur][tig + 4][r + 8]; alo[mi][3] = Al[cur][tig + 4][r + 8];
            }
            uint32_t bhi[4][2], blo[4][2];
#pragma unroll
            for (int ni = 0; ni < 4; ni++) {
                int cc = wn + ni * 8 + gid;
                bhi[ni][0] = Bh[cur][tig][cc];     blo[ni][0] = Bl[cur][tig][cc];
                bhi[ni][1] = Bh[cur][tig + 4][cc]; blo[ni][1] = Bl[cur][tig + 4][cc];
            }
#pragma unroll
            for (int mi = 0; mi < 4; mi++)
#pragma unroll
                for (int ni = 0; ni < 4; ni++) {
                    mma_bf16(acc[mi][ni], ahi[mi], bhi[ni]);
                    mma_bf16(acc[mi][ni], alo[mi], bhi[ni]);
                    mma_bf16(acc[mi][ni], ahi[mi], blo[ni]);
                }
        }
        if (c + 1 < nch) {
            __syncthreads();
            store_tiles(1 - cur);
            __syncthreads();
        }
    }

#pragma unroll
    for (int ni = 0; ni < 4; ni++) {
        int col = bn + wn + ni * 8 + tig * 2;
#pragma unroll
        for (int mi = 0; mi < 4; mi++) {
            int r0 = bm + wm + mi * 16 + gid;
            float2 v0 = make_float2(fmaxf(acc[mi][ni][0], 0.f), fmaxf(acc[mi][ni][1], 0.f));
            float2 v1 = make_float2(fmaxf(acc[mi][ni][2], 0.f), fmaxf(acc[mi][ni][3], 0.f));
            if (r0 < M) {
                int g = __ldg(batchmap + r0);
                red_add_v2(pool + (size_t)g * 256 + col, v0);
            }
            if (r0 + 8 < M) {
                int g = __ldg(batchmap + r0 + 8);
                red_add_v2(pool + (size_t)g * 256 + col, v1);
            }
        }
    }
}

__global__ void pred2(float* __restrict__ out) {
    int g = blockIdx.x;
    int k = threadIdx.x;
    __shared__ float p[256];
    p[k] = g_poolz[g * 256 + k];
    __syncthreads();
    if (k < NT) {
        const float* wf = g_wf + k * 256;
        float s = 0.f;
#pragma unroll 16
        for (int i = 0; i < 256; i++) s += p[i] * wf[i];
        float cnt = fmaxf((float)g_cnt[g], 1.f);
        out[g * NT + k] = s / cnt + g_bf[k];
    }
}

// ---------------- launch (single stream, union kernels) -----------------------
extern "C" void kernel_launch(void* const* d_in, const int* in_sizes, int n_in,
                              void* d_out, int out_size) {
    const int*   x        = (const int*)  d_in[0];
    const int*   ei       = (const int*)  d_in[1];
    const float* ea       = (const float*)d_in[2];
    const int*   batch    = (const int*)  d_in[3];
    const int*   sli      = (const int*)  d_in[4];
    const int*   slt      = (const int*)  d_in[5];
    const float* node_emb = (const float*)d_in[6];
    const float* L[2][10];
    for (int l = 0; l < 2; l++)
        for (int j = 0; j < 10; j++)
            L[l][j] = (const float*)d_in[7 + l * 10 + j];
    const float* pred_w = (const float*)d_in[27];
    const float* pred_b = (const float*)d_in[28];
    float* out = (float*)d_out;

    int N = in_sizes[0];
    int E = in_sizes[1] / 2;
    int B = (N + 255) / 256;
    int EB = (E + 255) / 256;
    int GA = (N + 127) / 128;

    float *p_agg, *p_w1ext, *p_poolz, *p_easum;
    int *p_cnt;
    cudaGetSymbolAddress((void**)&p_agg,   g_agg);
    cudaGetSymbolAddress((void**)&p_w1ext, g_w1ext);
    cudaGetSymbolAddress((void**)&p_poolz, g_poolz);
    cudaGetSymbolAddress((void**)&p_easum, g_easum);
    cudaGetSymbolAddress((void**)&p_cnt,   g_cnt);

    cudaMemsetAsync(p_easum, 0, (size_t)N * EAP * sizeof(float), 0);
    cudaMemsetAsync(p_poolz, 0, (size_t)NG * 2 * H * sizeof(float), 0);
    cudaMemsetAsync(p_cnt,   0, (size_t)NG * sizeof(int), 0);

    // edge_presum ++ prep_all (independent)
    front<<<EB + 414, 256>>>(ei, ea, x, E, node_emb,
                             L[0][0], L[0][1], L[0][2], L[0][3], L[0][4], L[0][5], L[0][6], L[0][7],
                             L[1][0], L[1][1], L[1][2], L[1][3], L[1][4], L[1][5], L[1][6], L[1][7],
                             L[1][8], L[1][9], pred_w, pred_b, sli, slt);

    // gemm_aff ++ scan1 (independent; both need front's outputs)
    gaff_scan<<<GA + B, 256>>>(x, L[0][8], L[0][9], batch, N);

    scan2<<<1, 256>>>(B);
    scatter<<<EB, 256>>>(ei, E);

    // layer 1: gather + pooled GEMM1
    aggregate<<<(N * 32 + 255) / 256, 256>>>(N, E);
    gemm_tc<<<dim3((N + 127) / 128, 2), 256>>>(
        p_agg, p_w1ext, N, 256, KEXT, batch, p_poolz);

    pred2<<<NG, 256>>>(out);
}